// round 3
// baseline (speedup 1.0000x reference)
#include <cuda_runtime.h>
#include <cuda_bf16.h>
#include <math.h>

#define BN_EPS 1e-3f
#define SLOPE  0.1f
#define CT     30.0f

typedef unsigned long long ull;

// ---------------- f32x2 packed helpers (Blackwell sm_103a) ----------------
__device__ __forceinline__ ull dup2(float v) {
    ull r; asm("mov.b64 %0, {%1, %1};" : "=l"(r) : "f"(v)); return r;
}
__device__ __forceinline__ void fma2(ull& d, ull a, ull b) {
    asm("fma.rn.f32x2 %0, %1, %2, %0;" : "+l"(d) : "l"(a), "l"(b));
}
__device__ __forceinline__ float2 unpk(ull a) {
    float2 f; asm("mov.b64 {%0, %1}, %2;" : "=f"(f.x), "=f"(f.y) : "l"(a)); return f;
}

// ---------------- scratch (device globals; no allocation allowed) ----------------
__device__ float g_h1[256 * 128 * 32 * 32];   // conv1 out
__device__ float g_h2[256 * 256 * 16 * 16];   // conv2 out
__device__ float g_data[256 * 4096];          // embeds
__device__ float g_muA[16 * 4096];
__device__ float g_muB[16 * 4096];
__device__ float g_r[256 * 16];
__device__ float g_w1t[27 * 128];
__device__ float g_w2t[1152 * 256];
__device__ float g_w3t[2304 * 64];

// =====================================================================
// weight transpose: out[ick*OC + oc] = in[oc*ICK + ick]
// =====================================================================
__global__ __launch_bounds__(256) void transpose_w_kernel(
    const float* __restrict__ in, float* __restrict__ out, int OC, int ICK)
{
    int i = blockIdx.x * 256 + threadIdx.x;
    if (i < OC * ICK) {
        int oc = i % OC, ick = i / OC;
        out[i] = in[oc * ICK + ick];
    }
}

// =====================================================================
// conv1: x[256,3,64,64] -> h1[256,128,32,32]
// grid(256, 8): 16 oc per block. block 256 threads: each thread 4 spatial
// (one oh, 4 consecutive ow) x 16 oc (8 f32x2 pairs over oc).
// padded smem input: 3 planes of 65 rows x 67 cols (halo zeroed).
// NOTE: C1_IN padded 13065 -> 13072 so w_s is 16-byte aligned (LDS.64 on it).
// =====================================================================
#define C1_W 67
#define C1_PLANE (65 * 67)     // 4355
#define C1_IN_RAW (3 * C1_PLANE) // 13065
#define C1_IN 13072              // padded to 16B alignment

__global__ __launch_bounds__(256, 2) void conv1_kernel(
    const float* __restrict__ x, const float* __restrict__ w1t,
    const float* __restrict__ bias, const float* __restrict__ g,
    const float* __restrict__ beta, const float* __restrict__ m,
    const float* __restrict__ v, float* __restrict__ out)
{
    extern __shared__ float sm[];
    float* in_s = sm;                 // 13072 (13065 used)
    float* w_s  = sm + C1_IN;         // 432  ([c][k][oc16] oc-contiguous), 16B-aligned
    float* sc_s = w_s + 432;          // 16
    float* sh_s = sc_s + 16;          // 16

    int img = blockIdx.x;
    int oc0 = blockIdx.y * 16;
    int tid = threadIdx.x;

    for (int i = tid; i < C1_IN_RAW; i += 256) in_s[i] = 0.f;
    const float* xin = x + img * 12288;
    for (int i = tid; i < 12288; i += 256) {
        int c = i >> 12, r = (i >> 6) & 63, q = i & 63;
        in_s[c * C1_PLANE + (r + 1) * C1_W + q + 1] = xin[i];
    }
    for (int i = tid; i < 432; i += 256) {
        int ocl = i & 15, ick = i >> 4;
        w_s[i] = w1t[ick * 128 + oc0 + ocl];
    }
    if (tid < 16) {
        int oc = oc0 + tid;
        float sc = g[oc] / sqrtf(v[oc] + BN_EPS);
        sc_s[tid] = sc;
        sh_s[tid] = beta[oc] - m[oc] * sc + bias[oc] * sc;
    }
    __syncthreads();

    int oh = tid >> 3;
    int ow0 = (tid & 7) * 4;

    ull acc[4][8];
#pragma unroll
    for (int i = 0; i < 4; i++)
#pragma unroll
        for (int j = 0; j < 8; j++) acc[i][j] = 0ull;

#pragma unroll
    for (int c = 0; c < 3; c++) {
        const float* pin = in_s + c * C1_PLANE + (2 * oh) * C1_W + 2 * ow0;
        const ull* pw = (const ull*)(w_s + c * 9 * 16);
#pragma unroll
        for (int kh = 0; kh < 3; kh++)
#pragma unroll
            for (int kw = 0; kw < 3; kw++) {
                const float* p = pin + kh * C1_W + kw;
                ull v0 = dup2(p[0]), v1 = dup2(p[2]), v2 = dup2(p[4]), v3 = dup2(p[6]);
                const ull* wp = pw + (kh * 3 + kw) * 8;
                ull w0 = wp[0], w1 = wp[1], w2 = wp[2], w3 = wp[3];
                ull w4 = wp[4], w5 = wp[5], w6 = wp[6], w7 = wp[7];
#define C1FMA(i, vv) \
                fma2(acc[i][0], vv, w0); fma2(acc[i][1], vv, w1); \
                fma2(acc[i][2], vv, w2); fma2(acc[i][3], vv, w3); \
                fma2(acc[i][4], vv, w4); fma2(acc[i][5], vv, w5); \
                fma2(acc[i][6], vv, w6); fma2(acc[i][7], vv, w7);
                C1FMA(0, v0) C1FMA(1, v1) C1FMA(2, v2) C1FMA(3, v3)
#undef C1FMA
            }
    }

#pragma unroll
    for (int j = 0; j < 8; j++) {
        float sc0 = sc_s[2 * j], sh0 = sh_s[2 * j];
        float sc1 = sc_s[2 * j + 1], sh1 = sh_s[2 * j + 1];
        float4 y0, y1;
        float* py0 = &y0.x; float* py1 = &y1.x;
#pragma unroll
        for (int i = 0; i < 4; i++) {
            float2 f = unpk(acc[i][j]);
            float a = f.x * sc0 + sh0; a = a > 0.f ? a : SLOPE * a;
            float b = f.y * sc1 + sh1; b = b > 0.f ? b : SLOPE * b;
            py0[i] = a; py1[i] = b;
        }
        int oc = oc0 + 2 * j;
        float4* o0 = (float4*)(out + ((img * 128 + oc) * 32 + oh) * 32 + ow0);
        float4* o1 = (float4*)(out + ((img * 128 + oc + 1) * 32 + oh) * 32 + ow0);
        *o0 = y0; *o1 = y1;
    }
}

// =====================================================================
// conv2: h1[256,128,32,32] -> h2[256,256,16,16]
// grid(256, 4): 64 oc per block. block 256 = 64 sg x 4 og.
// thread: 4 spatial (one oh, 4 consecutive ow) x 16 oc (8 pairs).
// ic chunks of 8, padded smem 33x35 per plane.
// C2_IN = 9240 floats = 36960 B, 16B-aligned -> w_s ull-aligned.
// =====================================================================
#define C2_W 35
#define C2_PLANE (33 * 35)     // 1155
#define C2_IN (8 * C2_PLANE)   // 9240
#define C2_WS (8 * 9 * 64)     // 4608

__global__ __launch_bounds__(256, 2) void conv2_kernel(
    const float* __restrict__ in, const float* __restrict__ w2t,
    const float* __restrict__ bias, const float* __restrict__ g,
    const float* __restrict__ beta, const float* __restrict__ m,
    const float* __restrict__ v, float* __restrict__ out)
{
    extern __shared__ float sm[];
    float* in_s = sm;            // 9240
    float* w_s  = sm + C2_IN;    // 4608  ([ic][k][oc64] oc-contiguous)

    int img = blockIdx.x;
    int oc0 = blockIdx.y * 64;
    int tid = threadIdx.x;
    int sg = tid & 63, og = tid >> 6;
    int oh = sg >> 2;
    int ow0 = (sg & 3) * 4;

    for (int i = tid; i < C2_IN; i += 256) in_s[i] = 0.f;

    ull acc[4][8];
#pragma unroll
    for (int i = 0; i < 4; i++)
#pragma unroll
        for (int j = 0; j < 8; j++) acc[i][j] = 0ull;

    for (int icb = 0; icb < 128; icb += 8) {
        __syncthreads();
        const float* ip = in + (img * 128 + icb) * 1024;
        for (int i = tid; i < 8192; i += 256) {
            int ic = i >> 10, r = (i >> 5) & 31, q = i & 31;
            in_s[ic * C2_PLANE + (r + 1) * C2_W + q + 1] = ip[i];
        }
        for (int i = tid; i < C2_WS; i += 256) {
            int ocl = i & 63, ick = i >> 6;
            w_s[i] = w2t[(icb * 9 + ick) * 256 + oc0 + ocl];
        }
        __syncthreads();

        for (int ic = 0; ic < 8; ic++) {
            const float* pin = in_s + ic * C2_PLANE + (2 * oh) * C2_W + 2 * ow0;
            const ull* pw = (const ull*)(w_s + ic * 9 * 64) + og * 8;
#pragma unroll
            for (int kh = 0; kh < 3; kh++)
#pragma unroll
                for (int kw = 0; kw < 3; kw++) {
                    const float* p = pin + kh * C2_W + kw;
                    ull v0 = dup2(p[0]), v1 = dup2(p[2]), v2 = dup2(p[4]), v3 = dup2(p[6]);
                    const ull* wp = pw + (kh * 3 + kw) * 32;
                    ull w0 = wp[0], w1 = wp[1], w2 = wp[2], w3 = wp[3];
                    ull w4 = wp[4], w5 = wp[5], w6 = wp[6], w7 = wp[7];
#define C2FMA(i, vv) \
                    fma2(acc[i][0], vv, w0); fma2(acc[i][1], vv, w1); \
                    fma2(acc[i][2], vv, w2); fma2(acc[i][3], vv, w3); \
                    fma2(acc[i][4], vv, w4); fma2(acc[i][5], vv, w5); \
                    fma2(acc[i][6], vv, w6); fma2(acc[i][7], vv, w7);
                    C2FMA(0, v0) C2FMA(1, v1) C2FMA(2, v2) C2FMA(3, v3)
#undef C2FMA
                }
        }
    }

#pragma unroll
    for (int j = 0; j < 8; j++) {
        int oc = oc0 + og * 16 + 2 * j;
        float sc0 = g[oc] / sqrtf(v[oc] + BN_EPS);
        float sh0 = beta[oc] - m[oc] * sc0 + bias[oc] * sc0;
        float sc1 = g[oc + 1] / sqrtf(v[oc + 1] + BN_EPS);
        float sh1 = beta[oc + 1] - m[oc + 1] * sc1 + bias[oc + 1] * sc1;
        float4 y0, y1;
        float* py0 = &y0.x; float* py1 = &y1.x;
#pragma unroll
        for (int i = 0; i < 4; i++) {
            float2 f = unpk(acc[i][j]);
            float a = f.x * sc0 + sh0; a = a > 0.f ? a : SLOPE * a;
            float b = f.y * sc1 + sh1; b = b > 0.f ? b : SLOPE * b;
            py0[i] = a; py1[i] = b;
        }
        float4* o0 = (float4*)(out + ((img * 256 + oc) * 16 + oh) * 16 + ow0);
        float4* o1 = (float4*)(out + ((img * 256 + oc + 1) * 16 + oh) * 16 + ow0);
        *o0 = y0; *o1 = y1;
    }
}

// =====================================================================
// conv3: h2[256,256,16,16] -> embeds g_data[256,4096] (feat = oc*64 + sp)
// grid(128 img-pairs, 2 oc-tiles of 32). block 256 = 64 sg x 4 og.
// thread: 1 spatial x 2 images x 8 oc (4 pairs). ic chunks of 8.
// padded smem 17x19 per (img,ic) plane. C3_IN = 5168 floats = 20672 B, aligned.
// =====================================================================
#define C3_W 19
#define C3_PLANE (17 * 19)          // 323
#define C3_IN (2 * 8 * C3_PLANE)    // 5168
#define C3_WS (8 * 9 * 32)          // 2304

__global__ __launch_bounds__(256, 2) void conv3_kernel(
    const float* __restrict__ in, const float* __restrict__ w3t,
    const float* __restrict__ bias, const float* __restrict__ g,
    const float* __restrict__ beta, const float* __restrict__ m,
    const float* __restrict__ v, float* __restrict__ out)
{
    extern __shared__ float sm[];
    float* in_s = sm;           // 5168
    float* w_s  = sm + C3_IN;   // 2304 ([ic][k][oc32])

    int img0 = blockIdx.x * 2;
    int ocB = blockIdx.y * 32;
    int tid = threadIdx.x;
    int sg = tid & 63, og = tid >> 6;
    int oh = sg >> 3, ow = sg & 7;
    int oc0 = ocB + og * 8;

    for (int i = tid; i < C3_IN; i += 256) in_s[i] = 0.f;

    ull acc[2][4];
#pragma unroll
    for (int im = 0; im < 2; im++)
#pragma unroll
        for (int j = 0; j < 4; j++) acc[im][j] = 0ull;

    for (int icb = 0; icb < 256; icb += 8) {
        __syncthreads();
        for (int i = tid; i < 4096; i += 256) {
            int im = i >> 11, rest = i & 2047;
            int ic = rest >> 8, r = (rest >> 4) & 15, q = i & 15;
            in_s[(im * 8 + ic) * C3_PLANE + (r + 1) * C3_W + q + 1] =
                in[((img0 + im) * 256 + icb + ic) * 256 + (rest & 255)];
        }
        for (int i = tid; i < C3_WS; i += 256) {
            int ocl = i & 31, ick = i >> 5;
            w_s[i] = w3t[(icb * 9 + ick) * 64 + ocB + ocl];
        }
        __syncthreads();

        for (int ic = 0; ic < 8; ic++) {
            const float* pin0 = in_s + ic * C3_PLANE + (2 * oh) * C3_W + 2 * ow;
            const float* pin1 = pin0 + 8 * C3_PLANE;
            const ull* pw = (const ull*)(w_s + ic * 9 * 32) + og * 4;
#pragma unroll
            for (int kh = 0; kh < 3; kh++)
#pragma unroll
                for (int kw = 0; kw < 3; kw++) {
                    int off = kh * C3_W + kw;
                    ull v0 = dup2(pin0[off]);
                    ull v1 = dup2(pin1[off]);
                    const ull* wp = pw + (kh * 3 + kw) * 16;
                    ull w0 = wp[0], w1 = wp[1], w2 = wp[2], w3 = wp[3];
                    fma2(acc[0][0], v0, w0); fma2(acc[0][1], v0, w1);
                    fma2(acc[0][2], v0, w2); fma2(acc[0][3], v0, w3);
                    fma2(acc[1][0], v1, w0); fma2(acc[1][1], v1, w1);
                    fma2(acc[1][2], v1, w2); fma2(acc[1][3], v1, w3);
                }
        }
    }

#pragma unroll
    for (int j = 0; j < 4; j++) {
        int oc = oc0 + 2 * j;
        float sc0 = g[oc] / sqrtf(v[oc] + BN_EPS);
        float sh0 = beta[oc] - m[oc] * sc0 + bias[oc] * sc0;
        float sc1 = g[oc + 1] / sqrtf(v[oc + 1] + BN_EPS);
        float sh1 = beta[oc + 1] - m[oc + 1] * sc1 + bias[oc + 1] * sc1;
#pragma unroll
        for (int im = 0; im < 2; im++) {
            float2 f = unpk(acc[im][j]);
            float a = f.x * sc0 + sh0; a = a > 0.f ? a : SLOPE * a;
            float b = f.y * sc1 + sh1; b = b > 0.f ? b : SLOPE * b;
            out[(img0 + im) * 4096 + oc * 64 + sg] = a;
            out[(img0 + im) * 4096 + (oc + 1) * 64 + sg] = b;
        }
    }
}

// =====================================================================
// row L2 normalize, in place. grid 256, block 256.
// =====================================================================
__global__ __launch_bounds__(256) void normalize_kernel(float* __restrict__ data)
{
    int row = blockIdx.x, tid = threadIdx.x;
    float* dr = data + row * 4096;
    float vals[16];
    float s = 0.f;
#pragma unroll
    for (int i = 0; i < 16; i++) {
        vals[i] = dr[tid + i * 256];
        s = fmaf(vals[i], vals[i], s);
    }
    __shared__ float sm[9];
    int lane = tid & 31, warp = tid >> 5;
#pragma unroll
    for (int off = 16; off > 0; off >>= 1) s += __shfl_down_sync(0xffffffffu, s, off);
    if (lane == 0) sm[warp] = s;
    __syncthreads();
    if (tid == 0) {
        float t = 0.f;
        for (int w = 0; w < 8; w++) t += sm[w];
        sm[8] = 1.f / sqrtf(t);
    }
    __syncthreads();
    float inv = sm[8];
#pragma unroll
    for (int i = 0; i < 16; i++) dr[tid + i * 256] = vals[i] * inv;
}

__global__ __launch_bounds__(256) void copy_kernel(const float* __restrict__ src, float* __restrict__ dst)
{
    int i = blockIdx.x * 256 + threadIdx.x;
    if (i < 16 * 4096) dst[i] = src[i];
}

// =====================================================================
// dist + softmax: r[row,k] = softmax_k(30 * data[row] . mu[k])
// =====================================================================
__global__ __launch_bounds__(256) void dist_softmax_kernel(
    const float* __restrict__ data, const float* __restrict__ mu, float* __restrict__ rout)
{
    int row = blockIdx.x, tid = threadIdx.x;
    const float* dr = data + row * 4096;
    float acc[16];
#pragma unroll
    for (int k = 0; k < 16; k++) acc[k] = 0.f;
#pragma unroll 4
    for (int i = 0; i < 16; i++) {
        int j = tid + i * 256;
        float dj = __ldg(dr + j);
#pragma unroll
        for (int k = 0; k < 16; k++) acc[k] = fmaf(dj, __ldg(mu + k * 4096 + j), acc[k]);
    }
    __shared__ float wsum[8][16];
    int lane = tid & 31, warp = tid >> 5;
#pragma unroll
    for (int k = 0; k < 16; k++) {
        float v = acc[k];
#pragma unroll
        for (int off = 16; off > 0; off >>= 1) v += __shfl_down_sync(0xffffffffu, v, off);
        if (lane == 0) wsum[warp][k] = v;
    }
    __syncthreads();
    if (tid == 0) {
        float d[16];
        float mx = -1e30f;
#pragma unroll
        for (int k = 0; k < 16; k++) {
            float s = 0.f;
            for (int w = 0; w < 8; w++) s += wsum[w][k];
            d[k] = CT * s;
            mx = fmaxf(mx, d[k]);
        }
        float sum = 0.f;
#pragma unroll
        for (int k = 0; k < 16; k++) { d[k] = expf(d[k] - mx); sum += d[k]; }
        float inv = 1.f / sum;
#pragma unroll
        for (int k = 0; k < 16; k++) rout[row * 16 + k] = d[k] * inv;
    }
}

// =====================================================================
// mu update: mu_out[k,f] = sum_n r[n,k] data[n,f] / sum_n r[n,k]
// =====================================================================
__global__ __launch_bounds__(256) void update_mu_kernel(
    const float* __restrict__ r, const float* __restrict__ data, float* __restrict__ mu_out)
{
    __shared__ float rs[256 * 16];
    __shared__ float inv_cs[16];
    int tid = threadIdx.x;
    int f = blockIdx.x * 256 + tid;
    for (int i = tid; i < 4096; i += 256) rs[i] = r[i];
    __syncthreads();
    if (tid < 16) {
        float s = 0.f;
        for (int n = 0; n < 256; n++) s += rs[n * 16 + tid];
        inv_cs[tid] = 1.f / s;
    }
    __syncthreads();

    float acc[16];
#pragma unroll
    for (int k = 0; k < 16; k++) acc[k] = 0.f;
    for (int n = 0; n < 256; n++) {
        float d = __ldg(data + n * 4096 + f);
#pragma unroll
        for (int k = 0; k < 16; k++) acc[k] = fmaf(rs[n * 16 + k], d, acc[k]);
    }
#pragma unroll
    for (int k = 0; k < 16; k++) mu_out[k * 4096 + f] = acc[k] * inv_cs[k];
}

// =====================================================================
// host
// =====================================================================
extern "C" void kernel_launch(void* const* d_in, const int* in_sizes, int n_in,
                              void* d_out, int out_size)
{
    const float* x   = (const float*)d_in[0];
    const float* w1  = (const float*)d_in[1];
    const float* b1  = (const float*)d_in[2];
    const float* g1  = (const float*)d_in[3];
    const float* be1 = (const float*)d_in[4];
    const float* m1  = (const float*)d_in[5];
    const float* v1  = (const float*)d_in[6];
    const float* w2  = (const float*)d_in[7];
    const float* b2  = (const float*)d_in[8];
    const float* g2  = (const float*)d_in[9];
    const float* be2 = (const float*)d_in[10];
    const float* m2  = (const float*)d_in[11];
    const float* v2  = (const float*)d_in[12];
    const float* w3  = (const float*)d_in[13];
    const float* b3  = (const float*)d_in[14];
    const float* g3  = (const float*)d_in[15];
    const float* be3 = (const float*)d_in[16];
    const float* m3  = (const float*)d_in[17];
    const float* v3  = (const float*)d_in[18];
    const float* mu0 = (const float*)d_in[19];

    float *h1, *h2, *data, *muA, *muB, *r, *w1t, *w2t, *w3t;
    cudaGetSymbolAddress((void**)&h1, g_h1);
    cudaGetSymbolAddress((void**)&h2, g_h2);
    cudaGetSymbolAddress((void**)&data, g_data);
    cudaGetSymbolAddress((void**)&muA, g_muA);
    cudaGetSymbolAddress((void**)&muB, g_muB);
    cudaGetSymbolAddress((void**)&r, g_r);
    cudaGetSymbolAddress((void**)&w1t, g_w1t);
    cudaGetSymbolAddress((void**)&w2t, g_w2t);
    cudaGetSymbolAddress((void**)&w3t, g_w3t);

    const int smem1 = (C1_IN + 432 + 32) * 4;
    const int smem2 = (C2_IN + C2_WS) * 4;
    const int smem3 = (C3_IN + C3_WS) * 4;
    cudaFuncSetAttribute(conv1_kernel, cudaFuncAttributeMaxDynamicSharedMemorySize, smem1);
    cudaFuncSetAttribute(conv2_kernel, cudaFuncAttributeMaxDynamicSharedMemorySize, smem2);
    cudaFuncSetAttribute(conv3_kernel, cudaFuncAttributeMaxDynamicSharedMemorySize, smem3);

    transpose_w_kernel<<<(128 * 27 + 255) / 256, 256>>>(w1, w1t, 128, 27);
    transpose_w_kernel<<<(256 * 1152 + 255) / 256, 256>>>(w2, w2t, 256, 1152);
    transpose_w_kernel<<<(64 * 2304 + 255) / 256, 256>>>(w3, w3t, 64, 2304);

    conv1_kernel<<<dim3(256, 8), 256, smem1>>>(x, w1t, b1, g1, be1, m1, v1, h1);
    conv2_kernel<<<dim3(256, 4), 256, smem2>>>(h1, w2t, b2, g2, be2, m2, v2, h2);
    conv3_kernel<<<dim3(128, 2), 256, smem3>>>(h2, w3t, b3, g3, be3, m3, v3, data);
    normalize_kernel<<<256, 256>>>(data);
    copy_kernel<<<256, 256>>>(mu0, muA);

    for (int it = 0; it < 11; it++) {
        dist_softmax_kernel<<<256, 256>>>(data, muA, r);
        update_mu_kernel<<<16, 256>>>(r, data, muB);
        float* t = muA; muA = muB; muB = t;
    }
    dist_softmax_kernel<<<256, 256>>>(data, muA, (float*)d_out);
}

// round 4
// speedup vs baseline: 1.5018x; 1.5018x over previous
#include <cuda_runtime.h>
#include <cuda_bf16.h>
#include <math.h>

#define BN_EPS 1e-3f
#define SLOPE  0.1f
#define CT     30.0f

typedef unsigned long long ull;

// ---------------- f32x2 packed helpers (Blackwell sm_103a) ----------------
__device__ __forceinline__ ull dup2(float v) {
    ull r; asm("mov.b64 %0, {%1, %1};" : "=l"(r) : "f"(v)); return r;
}
__device__ __forceinline__ void fma2(ull& d, ull a, ull b) {
    asm("fma.rn.f32x2 %0, %1, %2, %0;" : "+l"(d) : "l"(a), "l"(b));
}
__device__ __forceinline__ float2 unpk(ull a) {
    float2 f; asm("mov.b64 {%0, %1}, %2;" : "=f"(f.x), "=f"(f.y) : "l"(a)); return f;
}

// ---------------- scratch (device globals; no allocation allowed) ----------------
__device__ float g_h1[256 * 128 * 32 * 32];   // conv1 out
__device__ float g_h2[256 * 256 * 16 * 16];   // conv2 out
__device__ float g_data[256 * 4096];          // embeds
__device__ float g_muA[16 * 4096];
__device__ float g_muB[16 * 4096];
__device__ float g_r[256 * 16];
__device__ float g_w1t[27 * 128];
__device__ float g_w2t[1152 * 256];
__device__ float g_w3t[2304 * 64];

// =====================================================================
// weight transpose: out[ick*OC + oc] = in[oc*ICK + ick]
// =====================================================================
__global__ __launch_bounds__(256) void transpose_w_kernel(
    const float* __restrict__ in, float* __restrict__ out, int OC, int ICK)
{
    int i = blockIdx.x * 256 + threadIdx.x;
    if (i < OC * ICK) {
        int oc = i % OC, ick = i / OC;
        out[i] = in[oc * ICK + ick];
    }
}

// =====================================================================
// conv1: x[256,3,64,64] -> h1[256,128,32,32]
// grid(256, 8): 16 oc per block. block 256 threads: each thread 4 spatial
// (one oh, 4 consecutive ow) x 16 oc (8 f32x2 pairs over oc).
// padded smem input: 3 planes of 65 rows x 67 cols (halo zeroed).
// NOTE: C1_IN padded 13065 -> 13072 so w_s is 16-byte aligned (LDS.64 on it).
// =====================================================================
#define C1_W 67
#define C1_PLANE (65 * 67)     // 4355
#define C1_IN_RAW (3 * C1_PLANE) // 13065
#define C1_IN 13072              // padded to 16B alignment

__global__ __launch_bounds__(256, 2) void conv1_kernel(
    const float* __restrict__ x, const float* __restrict__ w1t,
    const float* __restrict__ bias, const float* __restrict__ g,
    const float* __restrict__ beta, const float* __restrict__ m,
    const float* __restrict__ v, float* __restrict__ out)
{
    extern __shared__ float sm[];
    float* in_s = sm;                 // 13072 (13065 used)
    float* w_s  = sm + C1_IN;         // 432  ([c][k][oc16] oc-contiguous), 16B-aligned
    float* sc_s = w_s + 432;          // 16
    float* sh_s = sc_s + 16;          // 16

    int img = blockIdx.x;
    int oc0 = blockIdx.y * 16;
    int tid = threadIdx.x;

    for (int i = tid; i < C1_IN_RAW; i += 256) in_s[i] = 0.f;
    const float* xin = x + img * 12288;
    for (int i = tid; i < 12288; i += 256) {
        int c = i >> 12, r = (i >> 6) & 63, q = i & 63;
        in_s[c * C1_PLANE + (r + 1) * C1_W + q + 1] = xin[i];
    }
    for (int i = tid; i < 432; i += 256) {
        int ocl = i & 15, ick = i >> 4;
        w_s[i] = w1t[ick * 128 + oc0 + ocl];
    }
    if (tid < 16) {
        int oc = oc0 + tid;
        float sc = g[oc] / sqrtf(v[oc] + BN_EPS);
        sc_s[tid] = sc;
        sh_s[tid] = beta[oc] - m[oc] * sc + bias[oc] * sc;
    }
    __syncthreads();

    int oh = tid >> 3;
    int ow0 = (tid & 7) * 4;

    ull acc[4][8];
#pragma unroll
    for (int i = 0; i < 4; i++)
#pragma unroll
        for (int j = 0; j < 8; j++) acc[i][j] = 0ull;

#pragma unroll
    for (int c = 0; c < 3; c++) {
        const float* pin = in_s + c * C1_PLANE + (2 * oh) * C1_W + 2 * ow0;
        const ull* pw = (const ull*)(w_s + c * 9 * 16);
#pragma unroll
        for (int kh = 0; kh < 3; kh++)
#pragma unroll
            for (int kw = 0; kw < 3; kw++) {
                const float* p = pin + kh * C1_W + kw;
                ull v0 = dup2(p[0]), v1 = dup2(p[2]), v2 = dup2(p[4]), v3 = dup2(p[6]);
                const ull* wp = pw + (kh * 3 + kw) * 8;
                ull w0 = wp[0], w1 = wp[1], w2 = wp[2], w3 = wp[3];
                ull w4 = wp[4], w5 = wp[5], w6 = wp[6], w7 = wp[7];
#define C1FMA(i, vv) \
                fma2(acc[i][0], vv, w0); fma2(acc[i][1], vv, w1); \
                fma2(acc[i][2], vv, w2); fma2(acc[i][3], vv, w3); \
                fma2(acc[i][4], vv, w4); fma2(acc[i][5], vv, w5); \
                fma2(acc[i][6], vv, w6); fma2(acc[i][7], vv, w7);
                C1FMA(0, v0) C1FMA(1, v1) C1FMA(2, v2) C1FMA(3, v3)
#undef C1FMA
            }
    }

#pragma unroll
    for (int j = 0; j < 8; j++) {
        float sc0 = sc_s[2 * j], sh0 = sh_s[2 * j];
        float sc1 = sc_s[2 * j + 1], sh1 = sh_s[2 * j + 1];
        float4 y0, y1;
        float* py0 = &y0.x; float* py1 = &y1.x;
#pragma unroll
        for (int i = 0; i < 4; i++) {
            float2 f = unpk(acc[i][j]);
            float a = f.x * sc0 + sh0; a = a > 0.f ? a : SLOPE * a;
            float b = f.y * sc1 + sh1; b = b > 0.f ? b : SLOPE * b;
            py0[i] = a; py1[i] = b;
        }
        int oc = oc0 + 2 * j;
        float4* o0 = (float4*)(out + ((img * 128 + oc) * 32 + oh) * 32 + ow0);
        float4* o1 = (float4*)(out + ((img * 128 + oc + 1) * 32 + oh) * 32 + ow0);
        *o0 = y0; *o1 = y1;
    }
}

// =====================================================================
// conv2: h1[256,128,32,32] -> h2[256,256,16,16]
// grid(256, 4): 64 oc per block. block 256 = 64 sg x 4 og.
// thread: 4 spatial (one oh, 4 consecutive ow) x 16 oc (8 pairs).
// ic chunks of 8, padded smem 33x35 per plane.
// C2_IN = 9240 floats = 36960 B, 16B-aligned -> w_s ull-aligned.
// =====================================================================
#define C2_W 35
#define C2_PLANE (33 * 35)     // 1155
#define C2_IN (8 * C2_PLANE)   // 9240
#define C2_WS (8 * 9 * 64)     // 4608

__global__ __launch_bounds__(256, 2) void conv2_kernel(
    const float* __restrict__ in, const float* __restrict__ w2t,
    const float* __restrict__ bias, const float* __restrict__ g,
    const float* __restrict__ beta, const float* __restrict__ m,
    const float* __restrict__ v, float* __restrict__ out)
{
    extern __shared__ float sm[];
    float* in_s = sm;            // 9240
    float* w_s  = sm + C2_IN;    // 4608  ([ic][k][oc64] oc-contiguous)

    int img = blockIdx.x;
    int oc0 = blockIdx.y * 64;
    int tid = threadIdx.x;
    int sg = tid & 63, og = tid >> 6;
    int oh = sg >> 2;
    int ow0 = (sg & 3) * 4;

    for (int i = tid; i < C2_IN; i += 256) in_s[i] = 0.f;

    ull acc[4][8];
#pragma unroll
    for (int i = 0; i < 4; i++)
#pragma unroll
        for (int j = 0; j < 8; j++) acc[i][j] = 0ull;

    for (int icb = 0; icb < 128; icb += 8) {
        __syncthreads();
        const float* ip = in + (img * 128 + icb) * 1024;
        for (int i = tid; i < 8192; i += 256) {
            int ic = i >> 10, r = (i >> 5) & 31, q = i & 31;
            in_s[ic * C2_PLANE + (r + 1) * C2_W + q + 1] = ip[i];
        }
        for (int i = tid; i < C2_WS; i += 256) {
            int ocl = i & 63, ick = i >> 6;
            w_s[i] = w2t[(icb * 9 + ick) * 256 + oc0 + ocl];
        }
        __syncthreads();

        for (int ic = 0; ic < 8; ic++) {
            const float* pin = in_s + ic * C2_PLANE + (2 * oh) * C2_W + 2 * ow0;
            const ull* pw = (const ull*)(w_s + ic * 9 * 64) + og * 8;
#pragma unroll
            for (int kh = 0; kh < 3; kh++)
#pragma unroll
                for (int kw = 0; kw < 3; kw++) {
                    const float* p = pin + kh * C2_W + kw;
                    ull v0 = dup2(p[0]), v1 = dup2(p[2]), v2 = dup2(p[4]), v3 = dup2(p[6]);
                    const ull* wp = pw + (kh * 3 + kw) * 32;
                    ull w0 = wp[0], w1 = wp[1], w2 = wp[2], w3 = wp[3];
                    ull w4 = wp[4], w5 = wp[5], w6 = wp[6], w7 = wp[7];
#define C2FMA(i, vv) \
                    fma2(acc[i][0], vv, w0); fma2(acc[i][1], vv, w1); \
                    fma2(acc[i][2], vv, w2); fma2(acc[i][3], vv, w3); \
                    fma2(acc[i][4], vv, w4); fma2(acc[i][5], vv, w5); \
                    fma2(acc[i][6], vv, w6); fma2(acc[i][7], vv, w7);
                    C2FMA(0, v0) C2FMA(1, v1) C2FMA(2, v2) C2FMA(3, v3)
#undef C2FMA
                }
        }
    }

#pragma unroll
    for (int j = 0; j < 8; j++) {
        int oc = oc0 + og * 16 + 2 * j;
        float sc0 = g[oc] / sqrtf(v[oc] + BN_EPS);
        float sh0 = beta[oc] - m[oc] * sc0 + bias[oc] * sc0;
        float sc1 = g[oc + 1] / sqrtf(v[oc + 1] + BN_EPS);
        float sh1 = beta[oc + 1] - m[oc + 1] * sc1 + bias[oc + 1] * sc1;
        float4 y0, y1;
        float* py0 = &y0.x; float* py1 = &y1.x;
#pragma unroll
        for (int i = 0; i < 4; i++) {
            float2 f = unpk(acc[i][j]);
            float a = f.x * sc0 + sh0; a = a > 0.f ? a : SLOPE * a;
            float b = f.y * sc1 + sh1; b = b > 0.f ? b : SLOPE * b;
            py0[i] = a; py1[i] = b;
        }
        float4* o0 = (float4*)(out + ((img * 256 + oc) * 16 + oh) * 16 + ow0);
        float4* o1 = (float4*)(out + ((img * 256 + oc + 1) * 16 + oh) * 16 + ow0);
        *o0 = y0; *o1 = y1;
    }
}

// =====================================================================
// conv3: h2[256,256,16,16] -> embeds g_data[256,4096] (feat = oc*64 + sp)
// grid(128 img-pairs, 2 oc-tiles of 32). block 256 = 64 sg x 4 og.
// thread: 1 spatial x 2 images x 8 oc (4 pairs). ic chunks of 8.
// padded smem 17x19 per (img,ic) plane. C3_IN = 5168 floats = 20672 B, aligned.
// =====================================================================
#define C3_W 19
#define C3_PLANE (17 * 19)          // 323
#define C3_IN (2 * 8 * C3_PLANE)    // 5168
#define C3_WS (8 * 9 * 32)          // 2304

__global__ __launch_bounds__(256, 2) void conv3_kernel(
    const float* __restrict__ in, const float* __restrict__ w3t,
    const float* __restrict__ bias, const float* __restrict__ g,
    const float* __restrict__ beta, const float* __restrict__ m,
    const float* __restrict__ v, float* __restrict__ out)
{
    extern __shared__ float sm[];
    float* in_s = sm;           // 5168
    float* w_s  = sm + C3_IN;   // 2304 ([ic][k][oc32])

    int img0 = blockIdx.x * 2;
    int ocB = blockIdx.y * 32;
    int tid = threadIdx.x;
    int sg = tid & 63, og = tid >> 6;
    int oh = sg >> 3, ow = sg & 7;
    int oc0 = ocB + og * 8;

    for (int i = tid; i < C3_IN; i += 256) in_s[i] = 0.f;

    ull acc[2][4];
#pragma unroll
    for (int im = 0; im < 2; im++)
#pragma unroll
        for (int j = 0; j < 4; j++) acc[im][j] = 0ull;

    for (int icb = 0; icb < 256; icb += 8) {
        __syncthreads();
        for (int i = tid; i < 4096; i += 256) {
            int im = i >> 11, rest = i & 2047;
            int ic = rest >> 8, r = (rest >> 4) & 15, q = i & 15;
            in_s[(im * 8 + ic) * C3_PLANE + (r + 1) * C3_W + q + 1] =
                in[((img0 + im) * 256 + icb + ic) * 256 + (rest & 255)];
        }
        for (int i = tid; i < C3_WS; i += 256) {
            int ocl = i & 31, ick = i >> 5;
            w_s[i] = w3t[(icb * 9 + ick) * 64 + ocB + ocl];
        }
        __syncthreads();

        for (int ic = 0; ic < 8; ic++) {
            const float* pin0 = in_s + ic * C3_PLANE + (2 * oh) * C3_W + 2 * ow;
            const float* pin1 = pin0 + 8 * C3_PLANE;
            const ull* pw = (const ull*)(w_s + ic * 9 * 32) + og * 4;
#pragma unroll
            for (int kh = 0; kh < 3; kh++)
#pragma unroll
                for (int kw = 0; kw < 3; kw++) {
                    int off = kh * C3_W + kw;
                    ull v0 = dup2(pin0[off]);
                    ull v1 = dup2(pin1[off]);
                    const ull* wp = pw + (kh * 3 + kw) * 16;
                    ull w0 = wp[0], w1 = wp[1], w2 = wp[2], w3 = wp[3];
                    fma2(acc[0][0], v0, w0); fma2(acc[0][1], v0, w1);
                    fma2(acc[0][2], v0, w2); fma2(acc[0][3], v0, w3);
                    fma2(acc[1][0], v1, w0); fma2(acc[1][1], v1, w1);
                    fma2(acc[1][2], v1, w2); fma2(acc[1][3], v1, w3);
                }
        }
    }

#pragma unroll
    for (int j = 0; j < 4; j++) {
        int oc = oc0 + 2 * j;
        float sc0 = g[oc] / sqrtf(v[oc] + BN_EPS);
        float sh0 = beta[oc] - m[oc] * sc0 + bias[oc] * sc0;
        float sc1 = g[oc + 1] / sqrtf(v[oc + 1] + BN_EPS);
        float sh1 = beta[oc + 1] - m[oc + 1] * sc1 + bias[oc + 1] * sc1;
#pragma unroll
        for (int im = 0; im < 2; im++) {
            float2 f = unpk(acc[im][j]);
            float a = f.x * sc0 + sh0; a = a > 0.f ? a : SLOPE * a;
            float b = f.y * sc1 + sh1; b = b > 0.f ? b : SLOPE * b;
            out[(img0 + im) * 4096 + oc * 64 + sg] = a;
            out[(img0 + im) * 4096 + (oc + 1) * 64 + sg] = b;
        }
    }
}

// =====================================================================
// row L2 normalize, in place. grid 256, block 256.
// =====================================================================
__global__ __launch_bounds__(256) void normalize_kernel(float* __restrict__ data)
{
    int row = blockIdx.x, tid = threadIdx.x;
    float* dr = data + row * 4096;
    float vals[16];
    float s = 0.f;
#pragma unroll
    for (int i = 0; i < 16; i++) {
        vals[i] = dr[tid + i * 256];
        s = fmaf(vals[i], vals[i], s);
    }
    __shared__ float sm[9];
    int lane = tid & 31, warp = tid >> 5;
#pragma unroll
    for (int off = 16; off > 0; off >>= 1) s += __shfl_down_sync(0xffffffffu, s, off);
    if (lane == 0) sm[warp] = s;
    __syncthreads();
    if (tid == 0) {
        float t = 0.f;
        for (int w = 0; w < 8; w++) t += sm[w];
        sm[8] = 1.f / sqrtf(t);
    }
    __syncthreads();
    float inv = sm[8];
#pragma unroll
    for (int i = 0; i < 16; i++) dr[tid + i * 256] = vals[i] * inv;
}

__global__ __launch_bounds__(256) void copy_kernel(const float* __restrict__ src, float* __restrict__ dst)
{
    int i = blockIdx.x * 256 + threadIdx.x;
    if (i < 16 * 4096) dst[i] = src[i];
}

// =====================================================================
// dist + softmax: r[row,k] = softmax_k(30 * data[row] . mu[k])
// =====================================================================
__global__ __launch_bounds__(256) void dist_softmax_kernel(
    const float* __restrict__ data, const float* __restrict__ mu, float* __restrict__ rout)
{
    int row = blockIdx.x, tid = threadIdx.x;
    const float* dr = data + row * 4096;
    float acc[16];
#pragma unroll
    for (int k = 0; k < 16; k++) acc[k] = 0.f;
#pragma unroll 4
    for (int i = 0; i < 16; i++) {
        int j = tid + i * 256;
        float dj = __ldg(dr + j);
#pragma unroll
        for (int k = 0; k < 16; k++) acc[k] = fmaf(dj, __ldg(mu + k * 4096 + j), acc[k]);
    }
    __shared__ float wsum[8][16];
    int lane = tid & 31, warp = tid >> 5;
#pragma unroll
    for (int k = 0; k < 16; k++) {
        float v = acc[k];
#pragma unroll
        for (int off = 16; off > 0; off >>= 1) v += __shfl_down_sync(0xffffffffu, v, off);
        if (lane == 0) wsum[warp][k] = v;
    }
    __syncthreads();
    if (tid == 0) {
        float d[16];
        float mx = -1e30f;
#pragma unroll
        for (int k = 0; k < 16; k++) {
            float s = 0.f;
            for (int w = 0; w < 8; w++) s += wsum[w][k];
            d[k] = CT * s;
            mx = fmaxf(mx, d[k]);
        }
        float sum = 0.f;
#pragma unroll
        for (int k = 0; k < 16; k++) { d[k] = expf(d[k] - mx); sum += d[k]; }
        float inv = 1.f / sum;
#pragma unroll
        for (int k = 0; k < 16; k++) rout[row * 16 + k] = d[k] * inv;
    }
}

// =====================================================================
// mu update: mu_out[k,f] = sum_n r[n,k] data[n,f] / sum_n r[n,k]
// =====================================================================
__global__ __launch_bounds__(256) void update_mu_kernel(
    const float* __restrict__ r, const float* __restrict__ data, float* __restrict__ mu_out)
{
    __shared__ float rs[256 * 16];
    __shared__ float inv_cs[16];
    int tid = threadIdx.x;
    int f = blockIdx.x * 256 + tid;
    for (int i = tid; i < 4096; i += 256) rs[i] = r[i];
    __syncthreads();
    if (tid < 16) {
        float s = 0.f;
        for (int n = 0; n < 256; n++) s += rs[n * 16 + tid];
        inv_cs[tid] = 1.f / s;
    }
    __syncthreads();

    float acc[16];
#pragma unroll
    for (int k = 0; k < 16; k++) acc[k] = 0.f;
    for (int n = 0; n < 256; n++) {
        float d = __ldg(data + n * 4096 + f);
#pragma unroll
        for (int k = 0; k < 16; k++) acc[k] = fmaf(rs[n * 16 + k], d, acc[k]);
    }
#pragma unroll
    for (int k = 0; k < 16; k++) mu_out[k * 4096 + f] = acc[k] * inv_cs[k];
}

// =====================================================================
// host
// =====================================================================
extern "C" void kernel_launch(void* const* d_in, const int* in_sizes, int n_in,
                              void* d_out, int out_size)
{
    const float* x   = (const float*)d_in[0];
    const float* w1  = (const float*)d_in[1];
    const float* b1  = (const float*)d_in[2];
    const float* g1  = (const float*)d_in[3];
    const float* be1 = (const float*)d_in[4];
    const float* m1  = (const float*)d_in[5];
    const float* v1  = (const float*)d_in[6];
    const float* w2  = (const float*)d_in[7];
    const float* b2  = (const float*)d_in[8];
    const float* g2  = (const float*)d_in[9];
    const float* be2 = (const float*)d_in[10];
    const float* m2  = (const float*)d_in[11];
    const float* v2  = (const float*)d_in[12];
    const float* w3  = (const float*)d_in[13];
    const float* b3  = (const float*)d_in[14];
    const float* g3  = (const float*)d_in[15];
    const float* be3 = (const float*)d_in[16];
    const float* m3  = (const float*)d_in[17];
    const float* v3  = (const float*)d_in[18];
    const float* mu0 = (const float*)d_in[19];

    float *h1, *h2, *data, *muA, *muB, *r, *w1t, *w2t, *w3t;
    cudaGetSymbolAddress((void**)&h1, g_h1);
    cudaGetSymbolAddress((void**)&h2, g_h2);
    cudaGetSymbolAddress((void**)&data, g_data);
    cudaGetSymbolAddress((void**)&muA, g_muA);
    cudaGetSymbolAddress((void**)&muB, g_muB);
    cudaGetSymbolAddress((void**)&r, g_r);
    cudaGetSymbolAddress((void**)&w1t, g_w1t);
    cudaGetSymbolAddress((void**)&w2t, g_w2t);
    cudaGetSymbolAddress((void**)&w3t, g_w3t);

    const int smem1 = (C1_IN + 432 + 32) * 4;
    const int smem2 = (C2_IN + C2_WS) * 4;
    const int smem3 = (C3_IN + C3_WS) * 4;
    cudaFuncSetAttribute(conv1_kernel, cudaFuncAttributeMaxDynamicSharedMemorySize, smem1);
    cudaFuncSetAttribute(conv2_kernel, cudaFuncAttributeMaxDynamicSharedMemorySize, smem2);
    cudaFuncSetAttribute(conv3_kernel, cudaFuncAttributeMaxDynamicSharedMemorySize, smem3);

    transpose_w_kernel<<<(128 * 27 + 255) / 256, 256>>>(w1, w1t, 128, 27);
    transpose_w_kernel<<<(256 * 1152 + 255) / 256, 256>>>(w2, w2t, 256, 1152);
    transpose_w_kernel<<<(64 * 2304 + 255) / 256, 256>>>(w3, w3t, 64, 2304);

    conv1_kernel<<<dim3(256, 8), 256, smem1>>>(x, w1t, b1, g1, be1, m1, v1, h1);
    conv2_kernel<<<dim3(256, 4), 256, smem2>>>(h1, w2t, b2, g2, be2, m2, v2, h2);
    conv3_kernel<<<dim3(128, 2), 256, smem3>>>(h2, w3t, b3, g3, be3, m3, v3, data);
    normalize_kernel<<<256, 256>>>(data);
    copy_kernel<<<256, 256>>>(mu0, muA);

    for (int it = 0; it < 11; it++) {
        dist_softmax_kernel<<<256, 256>>>(data, muA, r);
        update_mu_kernel<<<16, 256>>>(r, data, muB);
        float* t = muA; muA = muB; muB = t;
    }
    dist_softmax_kernel<<<256, 256>>>(data, muA, (float*)d_out);
}

// round 6
// speedup vs baseline: 1.7933x; 1.1941x over previous
#include <cuda_runtime.h>
#include <cuda_bf16.h>
#include <math.h>
#include <stdint.h>

#define BN_EPS 1e-3f
#define SLOPE  0.1f
#define CT     30.0f

// ============================ scratch globals ============================
__device__ float g_h1[256 * 128 * 1024];
__device__ float g_h2[256 * 256 * 256];
__device__ float g_data[256 * 4096];
__device__ float g_muA[16 * 4096];
__device__ float g_muB[16 * 4096];
__device__ float g_r[256 * 16];
__device__ __nv_bfloat16 g_A1[256 * 1024 * 128];
__device__ __nv_bfloat16 g_A2[65536ull * 2304];
__device__ __nv_bfloat16 g_A3[16384ull * 4608];
__device__ __nv_bfloat16 g_B1[128 * 128];
__device__ __nv_bfloat16 g_B2[256 * 2304];
__device__ __nv_bfloat16 g_B3[64 * 4608];

__device__ __forceinline__ void bf16_split(float x, unsigned short& h, unsigned short& l) {
    __nv_bfloat16 hb = __float2bfloat16(x);
    h = __bfloat16_as_ushort(hb);
    l = __bfloat16_as_ushort(__float2bfloat16(x - __bfloat162float(hb)));
}
__device__ __forceinline__ uint32_t smem_u32(const void* p) {
    uint32_t a;
    asm("{ .reg .u64 t; cvta.to.shared.u64 t, %1; cvt.u32.u64 %0, t; }" : "=r"(a) : "l"(p));
    return a;
}
__device__ __forceinline__ void cp_async16(uint32_t dst, const void* src) {
    asm volatile("cp.async.cg.shared.global [%0], [%1], 16;" :: "r"(dst), "l"(src));
}
__device__ __forceinline__ void ldsm_x4(uint32_t* f, uint32_t addr) {
    asm volatile("ldmatrix.sync.aligned.m8n8.x4.shared.b16 {%0,%1,%2,%3}, [%4];"
                 : "=r"(f[0]), "=r"(f[1]), "=r"(f[2]), "=r"(f[3]) : "r"(addr));
}
__device__ __forceinline__ void mma_bf16(float* d, const uint32_t* a, const uint32_t* b) {
    asm volatile(
        "mma.sync.aligned.m16n8k16.row.col.f32.bf16.bf16.f32 "
        "{%0,%1,%2,%3}, {%4,%5,%6,%7}, {%8,%9}, {%0,%1,%2,%3};"
        : "+f"(d[0]), "+f"(d[1]), "+f"(d[2]), "+f"(d[3])
        : "r"(a[0]), "r"(a[1]), "r"(a[2]), "r"(a[3]), "r"(b[0]), "r"(b[1]));
}

// ============================ weight prep ============================
__global__ __launch_bounds__(128) void prep_w1(const float* __restrict__ w, __nv_bfloat16* __restrict__ o)
{
    int oc = threadIdx.x;
    unsigned short h[27], l[27];
#pragma unroll
    for (int j = 0; j < 27; j++) bf16_split(w[oc * 27 + j], h[j], l[j]);
    __nv_bfloat16* row = o + oc * 128;
#pragma unroll
    for (int j = 0; j < 27; j++) {
        row[j]      = __ushort_as_bfloat16(h[j]);
        row[27 + j] = __ushort_as_bfloat16(l[j]);
        row[54 + j] = __ushort_as_bfloat16(h[j]);
    }
#pragma unroll
    for (int j = 81; j < 128; j++) row[j] = __ushort_as_bfloat16(0);
}
__global__ __launch_bounds__(256) void prep_w2(const float* __restrict__ w, __nv_bfloat16* __restrict__ o)
{
    int oc = blockIdx.x;
    for (int k = threadIdx.x; k < 1152; k += 256) {
        unsigned short h, l; bf16_split(w[oc * 1152 + k], h, l);
        o[oc * 2304 + k] = __ushort_as_bfloat16(h);
        o[oc * 2304 + 1152 + k] = __ushort_as_bfloat16(l);
    }
}
__global__ __launch_bounds__(256) void prep_w3(const float* __restrict__ w, __nv_bfloat16* __restrict__ o)
{
    int oc = blockIdx.x;
    for (int k = threadIdx.x; k < 2304; k += 256) {
        unsigned short h, l; bf16_split(w[oc * 2304 + k], h, l);
        o[oc * 4608 + k] = __ushort_as_bfloat16(h);
        o[oc * 4608 + 2304 + k] = __ushort_as_bfloat16(l);
    }
}

// ============================ im2col ============================
__global__ __launch_bounds__(256) void im2col1(const float* __restrict__ x, __nv_bfloat16* __restrict__ A)
{
    __shared__ float s[12288];
    int img = blockIdx.x, tid = threadIdx.x;
    const float* xin = x + img * 12288;
    for (int i = tid; i < 12288; i += 256) s[i] = xin[i];
    __syncthreads();
#pragma unroll
    for (int pp = 0; pp < 4; pp++) {
        int p = tid + pp * 256;
        int oh = p >> 5, ow = p & 31;
        uint32_t t[64];
#pragma unroll
        for (int i = 0; i < 64; i++) t[i] = 0;
#pragma unroll
        for (int j = 0; j < 27; j++) {
            int ic = j / 9, kk = j % 9, kh = kk / 3, kw = kk % 3;
            int ih = 2 * oh - 1 + kh, iw = 2 * ow - 1 + kw;
            float val = (ih >= 0 && ih < 64 && iw >= 0 && iw < 64) ? s[ic * 4096 + ih * 64 + iw] : 0.f;
            unsigned short h, l; bf16_split(val, h, l);
            t[j >> 1]        |= (uint32_t)h << ((j & 1) * 16);
            t[(j + 27) >> 1] |= (uint32_t)h << (((j + 27) & 1) * 16);
            t[(j + 54) >> 1] |= (uint32_t)l << (((j + 54) & 1) * 16);
        }
        uint4* row = (uint4*)(A + ((size_t)(img * 1024 + p)) * 128);
#pragma unroll
        for (int w = 0; w < 16; w++) row[w] = make_uint4(t[4*w], t[4*w+1], t[4*w+2], t[4*w+3]);
    }
}

__global__ __launch_bounds__(256) void im2col2(const float* __restrict__ in, __nv_bfloat16* __restrict__ A)
{
    __shared__ float s[8192];
    int img = blockIdx.x, tid = threadIdx.x;
    int p = tid, oh = p >> 4, ow = p & 15;
    char* rowb = (char*)(A + ((size_t)(img * 256 + p)) * 2304);
    for (int icb = 0; icb < 16; icb++) {
        __syncthreads();
        const float* ip = in + ((size_t)img * 128 + icb * 8) * 1024;
        for (int i = tid; i < 8192; i += 256) s[i] = ip[i];
        __syncthreads();
        uint32_t th[36], tl[36];
#pragma unroll
        for (int u = 0; u < 36; u++) {
            uint32_t hv = 0, lv = 0;
#pragma unroll
            for (int half = 0; half < 2; half++) {
                int j = 2 * u + half;
                int ic8 = j / 9, kk = j % 9, kh = kk / 3, kw = kk % 3;
                int ih = 2 * oh - 1 + kh, iw = 2 * ow - 1 + kw;
                float val = (ih >= 0 && ih < 32 && iw >= 0 && iw < 32) ? s[ic8 * 1024 + (ih << 5) + iw] : 0.f;
                unsigned short h, l; bf16_split(val, h, l);
                hv |= (uint32_t)h << (half * 16);
                lv |= (uint32_t)l << (half * 16);
            }
            th[u] = hv; tl[u] = lv;
        }
        uint4* oh4 = (uint4*)(rowb + icb * 144);
        uint4* ol4 = (uint4*)(rowb + 2304 + icb * 144);
#pragma unroll
        for (int w = 0; w < 9; w++) {
            oh4[w] = make_uint4(th[4*w], th[4*w+1], th[4*w+2], th[4*w+3]);
            ol4[w] = make_uint4(tl[4*w], tl[4*w+1], tl[4*w+2], tl[4*w+3]);
        }
    }
}

__global__ __launch_bounds__(256) void im2col3(const float* __restrict__ in, __nv_bfloat16* __restrict__ A)
{
    __shared__ float s[8192];
    int img = blockIdx.x, tid = threadIdx.x;
    int p = tid & 63, q = tid >> 6;
    int oh = p >> 3, ow = p & 7;
    char* rowb = (char*)(A + ((size_t)(img * 64 + p)) * 4608);
    for (int icb = 0; icb < 8; icb++) {
        __syncthreads();
        const float* ip = in + ((size_t)img * 256 + icb * 32) * 256;
        for (int i = tid; i < 8192; i += 256) s[i] = ip[i];
        __syncthreads();
        uint32_t th[36], tl[36];
#pragma unroll
        for (int u = 0; u < 36; u++) {
            uint32_t hv = 0, lv = 0;
#pragma unroll
            for (int half = 0; half < 2; half++) {
                int j = 2 * u + half;
                int ic8 = j / 9, kk = j % 9, kh = kk / 3, kw = kk % 3;
                int ih = 2 * oh - 1 + kh, iw = 2 * ow - 1 + kw;
                float val = (ih >= 0 && ih < 16 && iw >= 0 && iw < 16)
                                ? s[(q * 8 + ic8) * 256 + (ih << 4) + iw] : 0.f;
                unsigned short h, l; bf16_split(val, h, l);
                hv |= (uint32_t)h << (half * 16);
                lv |= (uint32_t)l << (half * 16);
            }
            th[u] = hv; tl[u] = lv;
        }
        uint4* oh4 = (uint4*)(rowb + icb * 576 + q * 144);
        uint4* ol4 = (uint4*)(rowb + 4608 + icb * 576 + q * 144);
#pragma unroll
        for (int w = 0; w < 9; w++) {
            oh4[w] = make_uint4(th[4*w], th[4*w+1], th[4*w+2], th[4*w+3]);
            ol4[w] = make_uint4(tl[4*w], tl[4*w+1], tl[4*w+2], tl[4*w+3]);
        }
    }
}

// ============================ HMMA GEMM (mma.sync bf16) ============================
// D[128 rows, BLOCK_N] = sum over NC chunks of A[128,64] . B[BLOCK_N,64]^T
// smem A/B tiles padded to stride 72 bf16 (144 B); cp.async double buffer.
template<int CONV>
__global__ __launch_bounds__(256)
void gemm_kernel(const __nv_bfloat16* __restrict__ A, const __nv_bfloat16* __restrict__ Bw,
                 const float* __restrict__ bias, const float* __restrict__ g,
                 const float* __restrict__ beta, const float* __restrict__ m,
                 const float* __restrict__ v, float* __restrict__ out)
{
    constexpr int N  = (CONV == 2) ? 256 : ((CONV == 1) ? 128 : 64);
    constexpr int NC = (CONV == 1) ? 2 : ((CONV == 2) ? 54 : 108);
    constexpr int KS = (CONV == 1) ? 128 : ((CONV == 2) ? 2304 : 4608);
    constexpr int HC = (CONV == 1) ? 2 : ((CONV == 2) ? 18 : 36);
    constexpr int BN = (N > 128) ? 128 : N;     // block N tile
    constexpr int WN = BN / 2;                  // warp N tile (64 or 32)
    constexpr int NT = WN / 8;                  // n8 tiles per warp (8 or 4)
    constexpr int ABUF = 128 * 144;             // bytes
    constexpr int BBUF = BN * 144;
    constexpr int BGI = (BN * 8) / 256;         // B cp.async iters per thread
    constexpr int P = BN + 1;                   // stage pitch (floats)

    extern __shared__ __align__(16) char smem[];
    __shared__ float scs[256], shs[256];

    int tid = threadIdx.x, wid = tid >> 5, lane = tid & 31;
    int wm = wid & 3, wn = wid >> 2;
    int rowbase = blockIdx.x * 128;
    int nb0 = blockIdx.y * BN;

    if (tid < N) {
        float sc = g[tid] / sqrtf(v[tid] + BN_EPS);
        scs[tid] = sc;
        shs[tid] = beta[tid] - m[tid] * sc + bias[tid] * sc;
    }

    uint32_t sb = smem_u32(smem);

    float acc[2][NT][4];
#pragma unroll
    for (int i = 0; i < 2; i++)
#pragma unroll
        for (int j = 0; j < NT; j++)
#pragma unroll
            for (int q = 0; q < 4; q++) acc[i][j][q] = 0.f;

    // chunk -> (Ai, Bi) schedule: hi.hi, hi.lo, lo.hi
    auto issue_copy = [&](int c) {
        int Ai = (c < HC) ? c : c - HC;
        int Bi = (c < 2 * HC) ? c : c - 2 * HC;
        int buf = c & 1;
        uint32_t ab = sb + buf * (ABUF + BBUF);
        uint32_t bb = ab + ABUF;
#pragma unroll
        for (int i = 0; i < 4; i++) {
            int gi = tid + 256 * i; int rr = gi >> 3, gc = gi & 7;
            cp_async16(ab + rr * 144 + gc * 16,
                       (const char*)A + ((size_t)(rowbase + rr) * KS + Ai * 64) * 2 + gc * 16);
        }
#pragma unroll
        for (int i = 0; i < BGI; i++) {
            int gi = tid + 256 * i; int rr = gi >> 3, gc = gi & 7;
            cp_async16(bb + rr * 144 + gc * 16,
                       (const char*)Bw + ((size_t)(nb0 + rr) * KS + Bi * 64) * 2 + gc * 16);
        }
        asm volatile("cp.async.commit_group;");
    };

    issue_copy(0);
    for (int c = 0; c < NC; c++) {
        if (c + 1 < NC) {
            issue_copy(c + 1);
            asm volatile("cp.async.wait_group 1;");
        } else {
            asm volatile("cp.async.wait_group 0;");
        }
        __syncthreads();

        int buf = c & 1;
        uint32_t ab = sb + buf * (ABUF + BBUF);
        uint32_t bb = ab + ABUF;
#pragma unroll
        for (int ks = 0; ks < 4; ks++) {
            uint32_t af[2][4];
#pragma unroll
            for (int mt = 0; mt < 2; mt++) {
                uint32_t addr = ab + (wm * 32 + mt * 16 + (lane & 15)) * 144
                                + ks * 32 + ((lane >> 4) << 4);
                ldsm_x4(af[mt], addr);
            }
#pragma unroll
            for (int nt2 = 0; nt2 < NT / 2; nt2++) {
                uint32_t bf[4];
                uint32_t addr = bb + (wn * WN + nt2 * 16 + (lane & 7) + (((lane >> 4) & 1) << 3)) * 144
                                + ks * 32 + (((lane >> 3) & 1) << 4);
                ldsm_x4(bf, addr);
#pragma unroll
                for (int mt = 0; mt < 2; mt++) {
                    mma_bf16(acc[mt][2 * nt2],     af[mt], bf);
                    mma_bf16(acc[mt][2 * nt2 + 1], af[mt], bf + 2);
                }
            }
        }
        __syncthreads();
    }

    // ---- epilogue: stage fp32 tile in smem, coalesced BN+LReLU writes ----
    float* stage = (float*)smem;
#pragma unroll
    for (int mt = 0; mt < 2; mt++)
#pragma unroll
        for (int nt = 0; nt < NT; nt++) {
            int r0 = wm * 32 + mt * 16 + (lane >> 2);
            int c0 = wn * WN + nt * 8 + 2 * (lane & 3);
            stage[r0 * P + c0]           = acc[mt][nt][0];
            stage[r0 * P + c0 + 1]       = acc[mt][nt][1];
            stage[(r0 + 8) * P + c0]     = acc[mt][nt][2];
            stage[(r0 + 8) * P + c0 + 1] = acc[mt][nt][3];
        }
    __syncthreads();

#pragma unroll
    for (int j = 0; j < BN / 8; j++) {
        int colL = wid * (BN / 8) + j;
        int gcol = nb0 + colL;
        float sc = scs[gcol], sh = shs[gcol];
#pragma unroll
        for (int it = 0; it < 4; it++) {
            int r = it * 32 + lane;
            float y = stage[r * P + colL] * sc + sh;
            y = y > 0.f ? y : SLOPE * y;
            int grow = rowbase + r;
            if (CONV == 1) {
                int img = grow >> 10, p = grow & 1023;
                out[((size_t)(img * 128 + gcol)) * 1024 + p] = y;
            } else if (CONV == 2) {
                int img = grow >> 8, p = grow & 255;
                out[((size_t)(img * 256 + gcol)) * 256 + p] = y;
            } else {
                int img = grow >> 6, p = grow & 63;
                out[(size_t)img * 4096 + gcol * 64 + p] = y;
            }
        }
    }
}

// ============================ k-means ============================
__global__ __launch_bounds__(256) void normalize_kernel(float* __restrict__ data)
{
    int row = blockIdx.x, tid = threadIdx.x;
    float* dr = data + row * 4096;
    float vals[16];
    float s = 0.f;
#pragma unroll
    for (int i = 0; i < 16; i++) { vals[i] = dr[tid + i * 256]; s = fmaf(vals[i], vals[i], s); }
    __shared__ float sm[9];
    int lane = tid & 31, warp = tid >> 5;
#pragma unroll
    for (int off = 16; off > 0; off >>= 1) s += __shfl_down_sync(0xffffffffu, s, off);
    if (lane == 0) sm[warp] = s;
    __syncthreads();
    if (tid == 0) {
        float t = 0.f;
        for (int w = 0; w < 8; w++) t += sm[w];
        sm[8] = 1.f / sqrtf(t);
    }
    __syncthreads();
    float inv = sm[8];
#pragma unroll
    for (int i = 0; i < 16; i++) dr[tid + i * 256] = vals[i] * inv;
}

__global__ __launch_bounds__(256) void copy_kernel(const float* __restrict__ src, float* __restrict__ dst)
{
    int i = blockIdx.x * 256 + threadIdx.x;
    if (i < 16 * 4096) dst[i] = src[i];
}

__global__ __launch_bounds__(256) void dist_softmax_kernel(
    const float* __restrict__ data, const float* __restrict__ mu, float* __restrict__ rout)
{
    int row = blockIdx.x, tid = threadIdx.x;
    const float* dr = data + row * 4096;
    float acc[16];
#pragma unroll
    for (int k = 0; k < 16; k++) acc[k] = 0.f;
#pragma unroll 4
    for (int i = 0; i < 16; i++) {
        int j = tid + i * 256;
        float dj = __ldg(dr + j);
#pragma unroll
        for (int k = 0; k < 16; k++) acc[k] = fmaf(dj, __ldg(mu + k * 4096 + j), acc[k]);
    }
    __shared__ float wsum[8][16];
    int lane = tid & 31, warp = tid >> 5;
#pragma unroll
    for (int k = 0; k < 16; k++) {
        float vv = acc[k];
#pragma unroll
        for (int off = 16; off > 0; off >>= 1) vv += __shfl_down_sync(0xffffffffu, vv, off);
        if (lane == 0) wsum[warp][k] = vv;
    }
    __syncthreads();
    if (tid == 0) {
        float d[16];
        float mx = -1e30f;
#pragma unroll
        for (int k = 0; k < 16; k++) {
            float s = 0.f;
            for (int w = 0; w < 8; w++) s += wsum[w][k];
            d[k] = CT * s;
            mx = fmaxf(mx, d[k]);
        }
        float sum = 0.f;
#pragma unroll
        for (int k = 0; k < 16; k++) { d[k] = expf(d[k] - mx); sum += d[k]; }
        float inv = 1.f / sum;
#pragma unroll
        for (int k = 0; k < 16; k++) rout[row * 16 + k] = d[k] * inv;
    }
}

__global__ __launch_bounds__(128) void update_mu_kernel(
    const float* __restrict__ r, const float* __restrict__ data, float* __restrict__ mu_out)
{
    __shared__ float rs[256 * 16];
    __shared__ float inv_cs[16];
    int tid = threadIdx.x;
    int f = blockIdx.x * 128 + tid;
    for (int i = tid; i < 4096; i += 128) rs[i] = r[i];
    __syncthreads();
    if (tid < 16) {
        float s = 0.f;
        for (int n = 0; n < 256; n++) s += rs[n * 16 + tid];
        inv_cs[tid] = 1.f / s;
    }
    __syncthreads();
    float acc[16];
#pragma unroll
    for (int k = 0; k < 16; k++) acc[k] = 0.f;
    for (int n = 0; n < 256; n++) {
        float d = __ldg(data + n * 4096 + f);
#pragma unroll
        for (int k = 0; k < 16; k++) acc[k] = fmaf(rs[n * 16 + k], d, acc[k]);
    }
#pragma unroll
    for (int k = 0; k < 16; k++) mu_out[k * 4096 + f] = acc[k] * inv_cs[k];
}

// ============================ host ============================
extern "C" void kernel_launch(void* const* d_in, const int* in_sizes, int n_in,
                              void* d_out, int out_size)
{
    const float* x   = (const float*)d_in[0];
    const float* w1  = (const float*)d_in[1];
    const float* b1  = (const float*)d_in[2];
    const float* g1  = (const float*)d_in[3];
    const float* be1 = (const float*)d_in[4];
    const float* m1  = (const float*)d_in[5];
    const float* v1  = (const float*)d_in[6];
    const float* w2  = (const float*)d_in[7];
    const float* b2  = (const float*)d_in[8];
    const float* g2  = (const float*)d_in[9];
    const float* be2 = (const float*)d_in[10];
    const float* m2  = (const float*)d_in[11];
    const float* v2  = (const float*)d_in[12];
    const float* w3  = (const float*)d_in[13];
    const float* b3  = (const float*)d_in[14];
    const float* g3  = (const float*)d_in[15];
    const float* be3 = (const float*)d_in[16];
    const float* m3  = (const float*)d_in[17];
    const float* v3  = (const float*)d_in[18];
    const float* mu0 = (const float*)d_in[19];

    float *h1, *h2, *data, *muA, *muB, *r;
    __nv_bfloat16 *A1, *A2, *A3, *B1, *B2, *B3;
    cudaGetSymbolAddress((void**)&h1, g_h1);
    cudaGetSymbolAddress((void**)&h2, g_h2);
    cudaGetSymbolAddress((void**)&data, g_data);
    cudaGetSymbolAddress((void**)&muA, g_muA);
    cudaGetSymbolAddress((void**)&muB, g_muB);
    cudaGetSymbolAddress((void**)&r, g_r);
    cudaGetSymbolAddress((void**)&A1, g_A1);
    cudaGetSymbolAddress((void**)&A2, g_A2);
    cudaGetSymbolAddress((void**)&A3, g_A3);
    cudaGetSymbolAddress((void**)&B1, g_B1);
    cudaGetSymbolAddress((void**)&B2, g_B2);
    cudaGetSymbolAddress((void**)&B3, g_B3);

    // dynamic smem: max(double-buffer, fp32 stage)
    const int smem12 = 2 * (128 * 144 + 128 * 144);              // 73728
    const int smem3  = 2 * (128 * 144 + 64 * 144);               // 55296
    cudaFuncSetAttribute(gemm_kernel<1>, cudaFuncAttributeMaxDynamicSharedMemorySize, smem12);
    cudaFuncSetAttribute(gemm_kernel<2>, cudaFuncAttributeMaxDynamicSharedMemorySize, smem12);
    cudaFuncSetAttribute(gemm_kernel<3>, cudaFuncAttributeMaxDynamicSharedMemorySize, smem3);

    prep_w1<<<1, 128>>>(w1, B1);
    prep_w2<<<256, 256>>>(w2, B2);
    prep_w3<<<64, 256>>>(w3, B3);

    im2col1<<<256, 256>>>(x, A1);
    gemm_kernel<1><<<dim3(2048, 1), 256, smem12>>>(A1, B1, b1, g1, be1, m1, v1, h1);
    im2col2<<<256, 256>>>(h1, A2);
    gemm_kernel<2><<<dim3(512, 2), 256, smem12>>>(A2, B2, b2, g2, be2, m2, v2, h2);
    im2col3<<<256, 256>>>(h2, A3);
    gemm_kernel<3><<<dim3(128, 1), 256, smem3>>>(A3, B3, b3, g3, be3, m3, v3, data);

    normalize_kernel<<<256, 256>>>(data);
    copy_kernel<<<256, 256>>>(mu0, muA);
    for (int it = 0; it < 11; it++) {
        dist_softmax_kernel<<<256, 256>>>(data, muA, r);
        update_mu_kernel<<<32, 128>>>(r, data, muB);
        float* t = muA; muA = muB; muB = t;
    }
    dist_softmax_kernel<<<256, 256>>>(data, muA, (float*)d_out);
}